// round 12
// baseline (speedup 1.0000x reference)
#include <cuda_runtime.h>

// Balanced-softmax loss, 2-kernel fused version:
//   K1: dtype-probe + label histogram
//   K2: weighted log-sum-exp rows + last-block finalize & state reset
// pred: [32768, 1000] fp32, target: [32768] int32 OR int64 (runtime-probed),
// out: 1 fp32 scalar.

#define NCLASS 1000
#define NROWS  32768
#define WARPS_PER_BLOCK 8
#define THREADS (WARPS_PER_BLOCK * 32)
#define NVEC 250  // 1000 / 4 float4 per row
#define MAIN_BLOCKS (NROWS / WARPS_PER_BLOCK)

// Static zero-init gives the first call its zeroed state; the last block of
// main_kernel re-zeroes everything for subsequent graph replays.
__device__ float    g_freq[NCLASS];
__device__ double   g_acc;
__device__ int      g_is64;
__device__ unsigned g_done;

__device__ __forceinline__ int clamp_class(int t) {
    t = t < 0 ? 0 : t;
    return t >= NCLASS ? NCLASS - 1 : t;
}

__device__ __forceinline__ int load_label(const int* __restrict__ t32, int i, int is64) {
    return clamp_class(is64 ? t32[2 * i] : t32[i]);
}

// Warp-0 dtype probe: int64 labels < 1000 have zero high words at odd int32
// indices (little-endian). 64 independent loads -> ~2 L2 round trips.
__device__ __forceinline__ int probe_is64(const int* __restrict__ t32, int lane) {
    int ok = (t32[2 * lane + 1] == 0) & (t32[2 * (lane + 32) + 1] == 0);
    unsigned m = __ballot_sync(0xffffffffu, ok);
    return m == 0xffffffffu;
}

__global__ void hist_kernel(const int* __restrict__ t32, int n) {
    __shared__ int s_is64;
    int tid = threadIdx.x;
    if (tid < 32) {
        int is64 = probe_is64(t32, tid);
        if (tid == 0) {
            s_is64 = is64;
            if (blockIdx.x == 0) g_is64 = is64;   // published for main_kernel
        }
    }
    __syncthreads();
    int is64 = s_is64;
    for (int i = blockIdx.x * blockDim.x + tid; i < n;
         i += gridDim.x * blockDim.x) {
        atomicAdd(&g_freq[load_label(t32, i, is64)], 1.0f);
    }
}

__global__ __launch_bounds__(THREADS) void main_kernel(
    const float* __restrict__ pred,
    const int* __restrict__ t32,
    float* __restrict__ out)
{
    __shared__ float4 s_freq[NVEC];
    __shared__ double s_part[WARPS_PER_BLOCK];
    __shared__ bool   s_last;

    int tid = threadIdx.x;
    for (int i = tid; i < NVEC; i += THREADS) {
        s_freq[i] = reinterpret_cast<const float4*>(g_freq)[i];
    }
    __syncthreads();

    int warp = tid >> 5;
    int lane = tid & 31;
    int row  = blockIdx.x * WARPS_PER_BLOCK + warp;

    const float4* p = reinterpret_cast<const float4*>(pred + (size_t)row * NCLASS);

    // Hoisted label + picked-logit loads: latency hides under the streaming loop.
    int   t  = (lane == 0) ? load_label(t32, row, g_is64) : 0;
    float pt = (lane == 0) ? __ldg(pred + (size_t)row * NCLASS + t) : 0.0f;

    // 4 independent accumulators; __ldcs = evict-first (read-once stream).
    float s0 = 0.0f, s1 = 0.0f, s2 = 0.0f, s3 = 0.0f;
    #pragma unroll 8
    for (int i = lane; i < NVEC; i += 32) {
        float4 v = __ldcs(p + i);     // coalesced 128B/warp segments
        float4 f = s_freq[i];
        s0 += __expf(v.x) * f.x;
        s1 += __expf(v.y) * f.y;
        s2 += __expf(v.z) * f.z;
        s3 += __expf(v.w) * f.w;
    }
    float sum = (s0 + s1) + (s2 + s3);

    #pragma unroll
    for (int o = 16; o > 0; o >>= 1)
        sum += __shfl_xor_sync(0xffffffffu, sum, o);

    if (lane == 0) {
        float ft = reinterpret_cast<const float*>(s_freq)[t];
        float term = pt + __logf(ft) - __logf(sum);
        s_part[warp] = (double)term;
    }
    __syncthreads();

    if (tid == 0) {
        double d = 0.0;
        #pragma unroll
        for (int w = 0; w < WARPS_PER_BLOCK; w++) d += s_part[w];
        atomicAdd(&g_acc, d);
        __threadfence();                       // g_acc visible before done-count
        unsigned prev = atomicAdd(&g_done, 1u);
        s_last = (prev == (unsigned)gridDim.x - 1u);
    }
    __syncthreads();

    if (s_last) {
        // Last block: finalize + reset all state for the next graph replay.
        __threadfence();                       // acquire all g_acc updates
        for (int i = tid; i < NCLASS; i += THREADS) g_freq[i] = 0.0f;
        if (tid == 0) {
            out[0] = (float)(-g_acc / (double)NROWS);
            g_acc  = 0.0;
            g_done = 0u;
        }
    }
}

extern "C" void kernel_launch(void* const* d_in, const int* in_sizes, int n_in,
                              void* d_out, int out_size) {
    const float* pred = (const float*)d_in[0];
    const int*   t32  = (const int*)d_in[1];
    float*       out  = (float*)d_out;

    hist_kernel<<<128, 256>>>(t32, NROWS);
    main_kernel<<<MAIN_BLOCKS, THREADS>>>(pred, t32, out);
}

// round 17
// speedup vs baseline: 1.3351x; 1.3351x over previous
#include <cuda_runtime.h>

// Balanced-softmax loss, persistent 2-kernel version.
// pred: [32768, 1000] fp32, target: [32768] int32 OR int64 (runtime-probed),
// out: 1 fp32 scalar.

#define NCLASS 1000
#define NROWS  32768
#define WARPS_PER_BLOCK 8
#define THREADS (WARPS_PER_BLOCK * 32)
#define NVEC 250                  // 1000 / 4 float4 per row
#define MAIN_BLOCKS 740           // 148 SMs x 5 blocks: exactly one wave
#define TOTAL_WARPS (MAIN_BLOCKS * WARPS_PER_BLOCK)

__device__ float    g_freq[NCLASS];
__device__ double   g_acc;
__device__ int      g_is64;
__device__ unsigned g_done;

__device__ __forceinline__ int clamp_class(int t) {
    t = t < 0 ? 0 : t;
    return t >= NCLASS ? NCLASS - 1 : t;
}

__device__ __forceinline__ int load_label(const int* __restrict__ t32, int i, int is64) {
    return clamp_class(is64 ? t32[2 * i] : t32[i]);
}

__device__ __forceinline__ int probe_is64(const int* __restrict__ t32, int lane) {
    int ok = (t32[2 * lane + 1] == 0) & (t32[2 * (lane + 32) + 1] == 0);
    unsigned m = __ballot_sync(0xffffffffu, ok);
    return m == 0xffffffffu;
}

__global__ void hist_kernel(const int* __restrict__ t32, int n) {
    __shared__ int s_is64;
    int tid = threadIdx.x;
    if (tid < 32) {
        int is64 = probe_is64(t32, tid);
        if (tid == 0) {
            s_is64 = is64;
            if (blockIdx.x == 0) g_is64 = is64;
        }
    }
    __syncthreads();
    int is64 = s_is64;
    for (int i = blockIdx.x * blockDim.x + tid; i < n;
         i += gridDim.x * blockDim.x) {
        atomicAdd(&g_freq[load_label(t32, i, is64)], 1.0f);
    }
}

__global__ __launch_bounds__(THREADS, 5) void main_kernel(
    const float* __restrict__ pred,
    const int* __restrict__ t32,
    float* __restrict__ out)
{
    __shared__ float4 s_freq[NVEC];
    __shared__ double s_part[WARPS_PER_BLOCK];
    __shared__ int    s_is64;
    __shared__ bool   s_last;

    int tid = threadIdx.x;
    for (int i = tid; i < NVEC; i += THREADS) {
        s_freq[i] = reinterpret_cast<const float4*>(g_freq)[i];
    }
    if (tid == 0) s_is64 = g_is64;
    __syncthreads();

    int warp  = tid >> 5;
    int lane  = tid & 31;
    int gwarp = blockIdx.x * WARPS_PER_BLOCK + warp;
    int is64  = s_is64;

    double acc = 0.0;   // per-warp (lane 0) accumulation across its rows

    for (int row = gwarp; row < NROWS; row += TOTAL_WARPS) {
        const float4* p = reinterpret_cast<const float4*>(pred + (size_t)row * NCLASS);

        // Label load early: latency hides under the batched row loads.
        int t = (lane == 0) ? load_label(t32, row, is64) : 0;

        // Batch ALL row loads before any compute -> MLP = 8 per thread.
        float4 a[8];
        #pragma unroll
        for (int r = 0; r < 8; r++) {
            int idx = lane + r * 32;
            if (idx < NVEC) a[r] = p[idx];
        }

        float s0 = 0.0f, s1 = 0.0f, s2 = 0.0f, s3 = 0.0f;
        #pragma unroll
        for (int r = 0; r < 8; r++) {
            int idx = lane + r * 32;
            if (idx < NVEC) {
                float4 f = s_freq[idx];
                s0 += __expf(a[r].x) * f.x;
                s1 += __expf(a[r].y) * f.y;
                s2 += __expf(a[r].z) * f.z;
                s3 += __expf(a[r].w) * f.w;
            }
        }
        float sum = (s0 + s1) + (s2 + s3);

        #pragma unroll
        for (int o = 16; o > 0; o >>= 1)
            sum += __shfl_xor_sync(0xffffffffu, sum, o);

        if (lane == 0) {
            // Row is hot in L1 from the batched loads -> near-hit gather.
            float pt = pred[(size_t)row * NCLASS + t];
            float ft = reinterpret_cast<const float*>(s_freq)[t];
            acc += (double)(pt + __logf(ft) - __logf(sum));
        }
    }

    if (lane == 0) s_part[warp] = acc;
    __syncthreads();

    if (tid == 0) {
        double d = 0.0;
        #pragma unroll
        for (int w = 0; w < WARPS_PER_BLOCK; w++) d += s_part[w];
        atomicAdd(&g_acc, d);
        __threadfence();
        unsigned prev = atomicAdd(&g_done, 1u);
        s_last = (prev == (unsigned)gridDim.x - 1u);
    }
    __syncthreads();

    if (s_last) {
        __threadfence();
        for (int i = tid; i < NCLASS; i += THREADS) g_freq[i] = 0.0f;
        if (tid == 0) {
            out[0] = (float)(-g_acc / (double)NROWS);
            g_acc  = 0.0;
            g_done = 0u;
        }
    }
}

extern "C" void kernel_launch(void* const* d_in, const int* in_sizes, int n_in,
                              void* d_out, int out_size) {
    const float* pred = (const float*)d_in[0];
    const int*   t32  = (const int*)d_in[1];
    float*       out  = (float*)d_out;

    hist_kernel<<<128, 256>>>(t32, NROWS);
    main_kernel<<<MAIN_BLOCKS, THREADS>>>(pred, t32, out);
}